// round 2
// baseline (speedup 1.0000x reference)
#include <cuda_runtime.h>
#include <math.h>

#define BB 2
#define SS 2048
#define DD 768
#define HH 12
#define DHD 64

// Scratch for Q, K, V in [B, H, S, Dh] layout (12.6 MB each)
__device__ float g_q[BB * HH * SS * DHD];
__device__ float g_k[BB * HH * SS * DHD];
__device__ float g_v[BB * HH * SS * DHD];

// ---------------------------------------------------------------------------
// QKV projection: C[m,n] = sum_k X[m,k] * W[n,k] + bias[n]
// M = B*S = 4096, N = D = 768, K = 768. blockIdx.z selects {q,k,v}.
// Output written directly in [B,H,S,Dh] layout.
// Classic 128x128x8 tile, 256 threads, 8x8 register blocking.
// ---------------------------------------------------------------------------
__global__ __launch_bounds__(256) void qkv_kernel(
    const float* __restrict__ X,
    const float* __restrict__ Wq, const float* __restrict__ bq,
    const float* __restrict__ Wk, const float* __restrict__ bk,
    const float* __restrict__ Wv, const float* __restrict__ bv)
{
    const float* W;
    const float* bias;
    float* out;
    if (blockIdx.z == 0)      { W = Wq; bias = bq; out = g_q; }
    else if (blockIdx.z == 1) { W = Wk; bias = bk; out = g_k; }
    else                      { W = Wv; bias = bv; out = g_v; }

    __shared__ __align__(16) float As[8][132];
    __shared__ __align__(16) float Bs[8][132];

    const int tid = threadIdx.x;
    const int m0 = blockIdx.y * 128;
    const int n0 = blockIdx.x * 128;

    const int ld_row = tid >> 1;        // 0..127
    const int ld_k   = (tid & 1) * 4;   // 0 or 4

    const int ty = tid >> 4, tx = tid & 15;
    const int r0 = ty * 4, c0 = tx * 4;

    float acc[8][8];
#pragma unroll
    for (int i = 0; i < 8; i++)
#pragma unroll
        for (int j = 0; j < 8; j++) acc[i][j] = 0.f;

    for (int k0 = 0; k0 < DD; k0 += 8) {
        float4 av = *(const float4*)&X[(size_t)(m0 + ld_row) * DD + k0 + ld_k];
        float4 bw = *(const float4*)&W[(size_t)(n0 + ld_row) * DD + k0 + ld_k];
        __syncthreads();
        As[ld_k + 0][ld_row] = av.x; As[ld_k + 1][ld_row] = av.y;
        As[ld_k + 2][ld_row] = av.z; As[ld_k + 3][ld_row] = av.w;
        Bs[ld_k + 0][ld_row] = bw.x; Bs[ld_k + 1][ld_row] = bw.y;
        Bs[ld_k + 2][ld_row] = bw.z; Bs[ld_k + 3][ld_row] = bw.w;
        __syncthreads();

#pragma unroll
        for (int k = 0; k < 8; k++) {
            float a[8], b[8];
            *(float4*)&a[0] = *(const float4*)&As[k][r0];
            *(float4*)&a[4] = *(const float4*)&As[k][r0 + 64];
            *(float4*)&b[0] = *(const float4*)&Bs[k][c0];
            *(float4*)&b[4] = *(const float4*)&Bs[k][c0 + 64];
#pragma unroll
            for (int i = 0; i < 8; i++)
#pragma unroll
                for (int j = 0; j < 8; j++)
                    acc[i][j] += a[i] * b[j];
        }
    }

    // Epilogue: add bias, scatter into [B,H,S,Dh]
#pragma unroll
    for (int i = 0; i < 8; i++) {
        int row = (i < 4) ? (r0 + i) : (64 + r0 + (i - 4));
        int m = m0 + row;
        int bb = m / SS;
        int s  = m % SS;
#pragma unroll
        for (int j = 0; j < 8; j++) {
            int col = (j < 4) ? (c0 + j) : (64 + c0 + (j - 4));
            int n = n0 + col;
            int h  = n / DHD;
            int dh = n % DHD;
            out[(((size_t)(bb * HH + h)) * SS + s) * DHD + dh] = acc[i][j] + bias[n];
        }
    }
}

// ---------------------------------------------------------------------------
// Fused attention (flash-style, single pass over K):
//   - 64 q-rows per block, loop over 32 kv-tiles of 64 keys
//   - S = Q@K^T * scale + res   -> streamed to scores_out (residual output)
//   - S += mask, online softmax (running max / sum, rescale accumulator)
//   - acc += P @ V ; final ctx = acc / l
// 256 threads as 16x16; each thread owns 4 rows x 4 strided cols.
// Shared tiles padded to 65 floats/row: all inner-loop LDS conflict-free.
// ---------------------------------------------------------------------------
__global__ __launch_bounds__(256) void attn_kernel(
    const float* __restrict__ res,
    const float* __restrict__ mask,
    float* __restrict__ scores_out,
    float* __restrict__ ctx_out)
{
    extern __shared__ float smraw[];
    float (*Qs)[65] = (float (*)[65])(smraw);
    float (*Ks)[65] = (float (*)[65])(smraw + 64 * 65);
    float (*Vs)[65] = (float (*)[65])(smraw + 2 * 64 * 65);
    float (*Ps)[65] = (float (*)[65])(smraw + 3 * 64 * 65);

    const int b  = blockIdx.z;
    const int h  = blockIdx.y;
    const int q0 = blockIdx.x * 64;

    const int tid = threadIdx.x;
    const int ty = tid >> 4, tx = tid & 15;
    const int r0 = ty * 4;

    const float* Qg = g_q + (size_t)(b * HH + h) * SS * DHD;
    const float* Kg = g_k + (size_t)(b * HH + h) * SS * DHD;
    const float* Vg = g_v + (size_t)(b * HH + h) * SS * DHD;

    const float* resb  = res        + (size_t)(b * HH + h) * SS * SS;
    float*       soutb = scores_out + (size_t)(b * HH + h) * SS * SS;
    const float* maskb = mask + (size_t)b * SS;

    // Load Q tile: 64 rows x 64 d, float4 from gmem, scalar stores (pad 65)
    for (int idx = tid; idx < 64 * 16; idx += 256) {
        int row = idx >> 4;
        int d4  = (idx & 15) * 4;
        float4 v = *(const float4*)&Qg[(size_t)(q0 + row) * DHD + d4];
        Qs[row][d4 + 0] = v.x; Qs[row][d4 + 1] = v.y;
        Qs[row][d4 + 2] = v.z; Qs[row][d4 + 3] = v.w;
    }

    float m_i[4], l_i[4], acc[4][4];
#pragma unroll
    for (int i = 0; i < 4; i++) {
        m_i[i] = -INFINITY;
        l_i[i] = 0.f;
#pragma unroll
        for (int j = 0; j < 4; j++) acc[i][j] = 0.f;
    }

    for (int kt = 0; kt < 32; kt++) {
        const int kbase = kt * 64;

        __syncthreads();  // previous-iteration P@V reads done before overwrite
        for (int idx = tid; idx < 64 * 16; idx += 256) {
            int row = idx >> 4;
            int d4  = (idx & 15) * 4;
            float4 kv = *(const float4*)&Kg[(size_t)(kbase + row) * DHD + d4];
            float4 vv = *(const float4*)&Vg[(size_t)(kbase + row) * DHD + d4];
            Ks[row][d4 + 0] = kv.x; Ks[row][d4 + 1] = kv.y;
            Ks[row][d4 + 2] = kv.z; Ks[row][d4 + 3] = kv.w;
            Vs[row][d4 + 0] = vv.x; Vs[row][d4 + 1] = vv.y;
            Vs[row][d4 + 2] = vv.z; Vs[row][d4 + 3] = vv.w;
        }
        __syncthreads();

        // S tile = Q @ K^T (rows r0+i, cols tx+16j)
        float s[4][4];
#pragma unroll
        for (int i = 0; i < 4; i++)
#pragma unroll
            for (int j = 0; j < 4; j++) s[i][j] = 0.f;

#pragma unroll 16
        for (int d = 0; d < 64; d++) {
            float qf[4], kf[4];
#pragma unroll
            for (int i = 0; i < 4; i++) qf[i] = Qs[r0 + i][d];
#pragma unroll
            for (int j = 0; j < 4; j++) kf[j] = Ks[tx + 16 * j][d];
#pragma unroll
            for (int i = 0; i < 4; i++)
#pragma unroll
                for (int j = 0; j < 4; j++)
                    s[i][j] += qf[i] * kf[j];
        }

        // scale + residual -> stream residual output; + mask; row max
        float mloc[4];
#pragma unroll
        for (int i = 0; i < 4; i++) {
            int row = q0 + r0 + i;
            const float* rrow = resb  + (size_t)row * SS + kbase;
            float*       orow = soutb + (size_t)row * SS + kbase;
            float rm = -INFINITY;
#pragma unroll
            for (int j = 0; j < 4; j++) {
                int c = tx + 16 * j;
                float v = s[i][j] * 0.125f + rrow[c];
                orow[c] = v;                       // scores_res_out (pre-mask)
                v += maskb[kbase + c];
                s[i][j] = v;
                rm = fmaxf(rm, v);
            }
#pragma unroll
            for (int o = 8; o > 0; o >>= 1)
                rm = fmaxf(rm, __shfl_xor_sync(0xffffffffu, rm, o));
            mloc[i] = rm;
        }

        // online softmax update + write P tile
#pragma unroll
        for (int i = 0; i < 4; i++) {
            float mnew  = fmaxf(m_i[i], mloc[i]);
            float alpha = __expf(m_i[i] - mnew);
            m_i[i] = mnew;
            float rs = 0.f;
#pragma unroll
            for (int j = 0; j < 4; j++) {
                float p = __expf(s[i][j] - mnew);
                Ps[r0 + i][tx + 16 * j] = p;
                rs += p;
            }
#pragma unroll
            for (int o = 8; o > 0; o >>= 1)
                rs += __shfl_xor_sync(0xffffffffu, rs, o);
            l_i[i] = l_i[i] * alpha + rs;
#pragma unroll
            for (int j = 0; j < 4; j++) acc[i][j] *= alpha;
        }
        __syncthreads();

        // acc += P @ V   (cols of acc are dh = tx+16j)
#pragma unroll 16
        for (int kk = 0; kk < 64; kk++) {
            float pf[4], vf[4];
#pragma unroll
            for (int i = 0; i < 4; i++) pf[i] = Ps[r0 + i][kk];
#pragma unroll
            for (int j = 0; j < 4; j++) vf[j] = Vs[kk][tx + 16 * j];
#pragma unroll
            for (int i = 0; i < 4; i++)
#pragma unroll
                for (int j = 0; j < 4; j++)
                    acc[i][j] += pf[i] * vf[j];
        }
    }

    // epilogue: ctx[b, s, h*64 + dh] = acc / l
#pragma unroll
    for (int i = 0; i < 4; i++) {
        float inv = 1.0f / l_i[i];
        int row = q0 + r0 + i;
#pragma unroll
        for (int j = 0; j < 4; j++) {
            int dh = tx + 16 * j;
            ctx_out[((size_t)(b * SS + row)) * DD + h * DHD + dh] = acc[i][j] * inv;
        }
    }
}

extern "C" void kernel_launch(void* const* d_in, const int* in_sizes, int n_in,
                              void* d_out, int out_size)
{
    const float* hs   = (const float*)d_in[0];
    const float* mask = (const float*)d_in[1];
    const float* res  = (const float*)d_in[2];
    const float* Wq   = (const float*)d_in[3];
    const float* bq   = (const float*)d_in[4];
    const float* Wk   = (const float*)d_in[5];
    const float* bk   = (const float*)d_in[6];
    const float* Wv   = (const float*)d_in[7];
    const float* bv   = (const float*)d_in[8];

    float* ctx_out    = (float*)d_out;
    float* scores_out = (float*)d_out + (size_t)BB * SS * DD;

    // QKV projection: grid (N/128, M/128, 3)
    dim3 g1(DD / 128, (BB * SS) / 128, 3);
    qkv_kernel<<<g1, 256>>>(hs, Wq, bq, Wk, bk, Wv, bv);

    // Fused attention
    size_t smem = (size_t)4 * 64 * 65 * sizeof(float);  // 66560 B
    cudaFuncSetAttribute(attn_kernel, cudaFuncAttributeMaxDynamicSharedMemorySize,
                         (int)smem);
    dim3 g2(SS / 64, HH, BB);
    attn_kernel<<<g2, 256, smem>>>(res, mask, scores_out, ctx_out);
}

// round 3
// speedup vs baseline: 1.8675x; 1.8675x over previous
#include <cuda_runtime.h>
#include <math.h>

#define BB 2
#define SS 2048
#define DD 768
#define HH 12
#define DHD 64

typedef unsigned long long ull;

// ---- packed f32x2 helpers (Blackwell sm_103a) ------------------------------
__device__ __forceinline__ ull pk2(float x, float y) {
    ull r;
    unsigned xb = __float_as_uint(x), yb = __float_as_uint(y);
    asm("mov.b64 %0, {%1, %2};" : "=l"(r) : "r"(xb), "r"(yb));
    return r;
}
__device__ __forceinline__ void upk2(float& lo, float& hi, ull v) {
    unsigned l, h;
    asm("mov.b64 {%0, %1}, %2;" : "=r"(l), "=r"(h) : "l"(v));
    lo = __uint_as_float(l); hi = __uint_as_float(h);
}
__device__ __forceinline__ void ffma2(ull& d, ull a, ull b) {
    asm("fma.rn.f32x2 %0, %1, %2, %0;" : "+l"(d) : "l"(a), "l"(b));
}
__device__ __forceinline__ void fmul2(ull& d, ull a) {
    asm("mul.rn.f32x2 %0, %0, %1;" : "+l"(d) : "l"(a));
}

// Scratch for Q, K, V in [B, H, S, Dh] layout
__device__ float g_q[BB * HH * SS * DHD];
__device__ float g_k[BB * HH * SS * DHD];
__device__ float g_v[BB * HH * SS * DHD];

// ---------------------------------------------------------------------------
// QKV projection: C[m,n] = sum_k X[m,k] * W[n,k] + bias[n]
// 128x128x8 tile, 256 threads, 8x8 per thread, column pairs packed f32x2.
// ---------------------------------------------------------------------------
__global__ __launch_bounds__(256) void qkv_kernel(
    const float* __restrict__ X,
    const float* __restrict__ Wq, const float* __restrict__ bq,
    const float* __restrict__ Wk, const float* __restrict__ bk,
    const float* __restrict__ Wv, const float* __restrict__ bv)
{
    const float* W;
    const float* bias;
    float* out;
    if (blockIdx.z == 0)      { W = Wq; bias = bq; out = g_q; }
    else if (blockIdx.z == 1) { W = Wk; bias = bk; out = g_k; }
    else                      { W = Wv; bias = bv; out = g_v; }

    __shared__ __align__(16) float As[8][132];
    __shared__ __align__(16) float Bs[8][132];

    const int tid = threadIdx.x;
    const int m0 = blockIdx.y * 128;
    const int n0 = blockIdx.x * 128;

    const int ld_row = tid >> 1;
    const int ld_k   = (tid & 1) * 4;

    const int ty = tid >> 4, tx = tid & 15;
    const int r0 = ty * 4, c0 = tx * 4;

    ull acc2[8][4];
#pragma unroll
    for (int i = 0; i < 8; i++)
#pragma unroll
        for (int j = 0; j < 4; j++) acc2[i][j] = 0ULL;

    for (int k0 = 0; k0 < DD; k0 += 8) {
        float4 av = *(const float4*)&X[(size_t)(m0 + ld_row) * DD + k0 + ld_k];
        float4 bw = *(const float4*)&W[(size_t)(n0 + ld_row) * DD + k0 + ld_k];
        __syncthreads();
        As[ld_k + 0][ld_row] = av.x; As[ld_k + 1][ld_row] = av.y;
        As[ld_k + 2][ld_row] = av.z; As[ld_k + 3][ld_row] = av.w;
        Bs[ld_k + 0][ld_row] = bw.x; Bs[ld_k + 1][ld_row] = bw.y;
        Bs[ld_k + 2][ld_row] = bw.z; Bs[ld_k + 3][ld_row] = bw.w;
        __syncthreads();

#pragma unroll
        for (int k = 0; k < 8; k++) {
            float a[8];
            *(float4*)&a[0] = *(const float4*)&As[k][r0];
            *(float4*)&a[4] = *(const float4*)&As[k][r0 + 64];
            ull b0 = *(const ull*)&Bs[k][c0];
            ull b1 = *(const ull*)&Bs[k][c0 + 2];
            ull b2 = *(const ull*)&Bs[k][c0 + 64];
            ull b3 = *(const ull*)&Bs[k][c0 + 66];
#pragma unroll
            for (int i = 0; i < 8; i++) {
                ull aa = pk2(a[i], a[i]);
                ffma2(acc2[i][0], aa, b0);
                ffma2(acc2[i][1], aa, b1);
                ffma2(acc2[i][2], aa, b2);
                ffma2(acc2[i][3], aa, b3);
            }
        }
    }

    // Epilogue: unpack, add bias, scatter into [B,H,S,Dh]
#pragma unroll
    for (int i = 0; i < 8; i++) {
        int row = (i < 4) ? (r0 + i) : (64 + r0 + (i - 4));
        int m = m0 + row;
        int bb = m / SS;
        int s  = m % SS;
        float c[8];
        upk2(c[0], c[1], acc2[i][0]);
        upk2(c[2], c[3], acc2[i][1]);
        upk2(c[4], c[5], acc2[i][2]);
        upk2(c[6], c[7], acc2[i][3]);
#pragma unroll
        for (int j = 0; j < 8; j++) {
            int col = (j < 4) ? (c0 + j) : (64 + c0 + (j - 4));
            int n = n0 + col;
            int h  = n / DHD;
            int dh = n % DHD;
            out[(((size_t)(bb * HH + h)) * SS + s) * DHD + dh] = c[j] + bias[n];
        }
    }
}

// ---------------------------------------------------------------------------
// Fused flash attention with f32x2:
//   64 q-rows per block, 128 threads (ty=tid>>4 in 0..7, tx=tid&15).
//   Thread owns rows {ty+8i | i<8} x cols {4tx..4tx+3} (two f32x2 pairs).
//   Strided row ownership -> all column-direction smem reads are
//   2-address broadcasts on distinct banks (pitch 68).
// ---------------------------------------------------------------------------
#define PT 68   // smem pitch (floats): 68*4 % 16 == 0, 68 % 32 == 4

__global__ __launch_bounds__(128, 3) void attn_kernel(
    const float* __restrict__ res,
    const float* __restrict__ mask,
    float* __restrict__ scores_out,
    float* __restrict__ ctx_out)
{
    extern __shared__ float sm[];
    float (*Qs)[PT] = (float (*)[PT])(sm);                 // [row][d]
    float (*Kt)[PT] = (float (*)[PT])(sm + 64 * PT);       // [d][kcol]  (transposed)
    float (*Vs)[PT] = (float (*)[PT])(sm + 2 * 64 * PT);   // [krow][dh]
    float (*Ps)[PT] = (float (*)[PT])(sm + 3 * 64 * PT);   // [row][kcol]

    const int b  = blockIdx.z;
    const int h  = blockIdx.y;
    const int q0 = blockIdx.x * 64;

    const int tid = threadIdx.x;
    const int ty = tid >> 4, tx = tid & 15;
    const int c0 = tx * 4;

    const float* Qg = g_q + (size_t)(b * HH + h) * SS * DHD;
    const float* Kg = g_k + (size_t)(b * HH + h) * SS * DHD;
    const float* Vg = g_v + (size_t)(b * HH + h) * SS * DHD;

    const float* resb  = res        + (size_t)(b * HH + h) * SS * SS;
    float*       soutb = scores_out + (size_t)(b * HH + h) * SS * SS;
    const float* maskb = mask + (size_t)b * SS;

    // Load Q tile [64][64]
#pragma unroll
    for (int g = 0; g < 8; g++) {
        int item = tid + 128 * g;
        int row = item >> 4;
        int d4  = (item & 15) * 4;
        *(float4*)&Qs[row][d4] = *(const float4*)&Qg[(size_t)(q0 + row) * DHD + d4];
    }

    float m_i[8], l_i[8];
    ull acc2[8][2];
#pragma unroll
    for (int i = 0; i < 8; i++) {
        m_i[i] = -INFINITY;
        l_i[i] = 0.f;
        acc2[i][0] = 0ULL; acc2[i][1] = 0ULL;
    }

    for (int kt = 0; kt < 32; kt++) {
        const int kbase = kt * 64;

        __syncthreads();   // A: prev P@V done with Vs; QK(first iter) waits for Qs
        // Fill K (transposed) and V
#pragma unroll
        for (int g = 0; g < 8; g++) {
            int item = tid + 128 * g;
            int row = item >> 4;
            int d4  = (item & 15) * 4;
            float4 kv = *(const float4*)&Kg[(size_t)(kbase + row) * DHD + d4];
            float4 vv = *(const float4*)&Vg[(size_t)(kbase + row) * DHD + d4];
            Kt[d4 + 0][row] = kv.x; Kt[d4 + 1][row] = kv.y;
            Kt[d4 + 2][row] = kv.z; Kt[d4 + 3][row] = kv.w;
            *(float4*)&Vs[row][d4] = vv;
        }
        __syncthreads();   // B

        // S = Q @ K^T : s2[i][p] = packed cols (c0+2p, c0+2p+1)
        ull s2[8][2];
#pragma unroll
        for (int i = 0; i < 8; i++) { s2[i][0] = 0ULL; s2[i][1] = 0ULL; }

#pragma unroll 8
        for (int d = 0; d < 64; d++) {
            ull k0 = *(const ull*)&Kt[d][c0];
            ull k1 = *(const ull*)&Kt[d][c0 + 2];
#pragma unroll
            for (int i = 0; i < 8; i++) {
                float q = Qs[ty + 8 * i][d];
                ull qq = pk2(q, q);
                ffma2(s2[i][0], qq, k0);
                ffma2(s2[i][1], qq, k1);
            }
        }

        // residual stream + mask + online softmax
        float4 mv = *(const float4*)&maskb[kbase + c0];
#pragma unroll
        for (int i = 0; i < 8; i++) {
            int rl = ty + 8 * i;
            size_t roff = (size_t)(q0 + rl) * SS + kbase + c0;
            float v0, v1, v2, v3;
            upk2(v0, v1, s2[i][0]);
            upk2(v2, v3, s2[i][1]);
            float4 rr = *(const float4*)&resb[roff];
            v0 = fmaf(v0, 0.125f, rr.x);
            v1 = fmaf(v1, 0.125f, rr.y);
            v2 = fmaf(v2, 0.125f, rr.z);
            v3 = fmaf(v3, 0.125f, rr.w);
            *(float4*)&soutb[roff] = make_float4(v0, v1, v2, v3);
            v0 += mv.x; v1 += mv.y; v2 += mv.z; v3 += mv.w;

            float rm = fmaxf(fmaxf(v0, v1), fmaxf(v2, v3));
#pragma unroll
            for (int o = 8; o > 0; o >>= 1)
                rm = fmaxf(rm, __shfl_xor_sync(0xffffffffu, rm, o));

            float mnew  = fmaxf(m_i[i], rm);
            float alpha = __expf(m_i[i] - mnew);
            m_i[i] = mnew;

            float p0 = __expf(v0 - mnew);
            float p1 = __expf(v1 - mnew);
            float p2 = __expf(v2 - mnew);
            float p3 = __expf(v3 - mnew);
            *(float4*)&Ps[rl][c0] = make_float4(p0, p1, p2, p3);

            float rs = (p0 + p1) + (p2 + p3);
#pragma unroll
            for (int o = 8; o > 0; o >>= 1)
                rs += __shfl_xor_sync(0xffffffffu, rs, o);
            l_i[i] = l_i[i] * alpha + rs;

            ull aa = pk2(alpha, alpha);
            fmul2(acc2[i][0], aa);
            fmul2(acc2[i][1], aa);
        }
        __syncthreads();   // C: Ps complete

        // acc += P @ V
#pragma unroll 8
        for (int kk = 0; kk < 64; kk++) {
            ull w0 = *(const ull*)&Vs[kk][c0];
            ull w1 = *(const ull*)&Vs[kk][c0 + 2];
#pragma unroll
            for (int i = 0; i < 8; i++) {
                float p = Ps[ty + 8 * i][kk];
                ull pp = pk2(p, p);
                ffma2(acc2[i][0], pp, w0);
                ffma2(acc2[i][1], pp, w1);
            }
        }
    }

    // epilogue
#pragma unroll
    for (int i = 0; i < 8; i++) {
        int rl = ty + 8 * i;
        float inv = 1.0f / l_i[i];
        float a0, a1, a2, a3;
        upk2(a0, a1, acc2[i][0]);
        upk2(a2, a3, acc2[i][1]);
        float4 o = make_float4(a0 * inv, a1 * inv, a2 * inv, a3 * inv);
        *(float4*)&ctx_out[((size_t)(b * SS + q0 + rl)) * DD + h * DHD + c0] = o;
    }
}

extern "C" void kernel_launch(void* const* d_in, const int* in_sizes, int n_in,
                              void* d_out, int out_size)
{
    const float* hs   = (const float*)d_in[0];
    const float* mask = (const float*)d_in[1];
    const float* res  = (const float*)d_in[2];
    const float* Wq   = (const float*)d_in[3];
    const float* bq   = (const float*)d_in[4];
    const float* Wk   = (const float*)d_in[5];
    const float* bk   = (const float*)d_in[6];
    const float* Wv   = (const float*)d_in[7];
    const float* bv   = (const float*)d_in[8];

    float* ctx_out    = (float*)d_out;
    float* scores_out = (float*)d_out + (size_t)BB * SS * DD;

    dim3 g1(DD / 128, (BB * SS) / 128, 3);
    qkv_kernel<<<g1, 256>>>(hs, Wq, bq, Wk, bk, Wv, bv);

    size_t smem = (size_t)4 * 64 * PT * sizeof(float);   // 69632 B
    cudaFuncSetAttribute(attn_kernel, cudaFuncAttributeMaxDynamicSharedMemorySize,
                         (int)smem);
    dim3 g2(SS / 64, HH, BB);
    attn_kernel<<<g2, 128, smem>>>(res, mask, scores_out, ctx_out);
}

// round 6
// speedup vs baseline: 2.9981x; 1.6054x over previous
#include <cuda_runtime.h>
#include <math.h>
#include <cstdint>

#define BB 2
#define SS 2048
#define DD 768
#define HH 12
#define DHD 64

typedef unsigned long long ull;

// ---- packed f32x2 helpers (QKV kernel) -------------------------------------
__device__ __forceinline__ ull pk2(float x, float y) {
    ull r;
    unsigned xb = __float_as_uint(x), yb = __float_as_uint(y);
    asm("mov.b64 %0, {%1, %2};" : "=l"(r) : "r"(xb), "r"(yb));
    return r;
}
__device__ __forceinline__ void upk2(float& lo, float& hi, ull v) {
    unsigned l, h;
    asm("mov.b64 {%0, %1}, %2;" : "=r"(l), "=r"(h) : "l"(v));
    lo = __uint_as_float(l); hi = __uint_as_float(h);
}
__device__ __forceinline__ void ffma2(ull& d, ull a, ull b) {
    asm("fma.rn.f32x2 %0, %1, %2, %0;" : "+l"(d) : "l"(a), "l"(b));
}

// ---- tf32 helpers ----------------------------------------------------------
__device__ __forceinline__ uint32_t tf32_of(float f) {
    uint32_t u;
    asm("cvt.rna.tf32.f32 %0, %1;" : "=r"(u) : "f"(f));
    return u;
}
__device__ __forceinline__ void mma_tf32(float* d,
                                         uint32_t a0, uint32_t a1, uint32_t a2, uint32_t a3,
                                         uint32_t b0, uint32_t b1) {
    asm volatile(
        "mma.sync.aligned.m16n8k8.row.col.f32.tf32.tf32.f32 "
        "{%0,%1,%2,%3}, {%4,%5,%6,%7}, {%8,%9}, {%0,%1,%2,%3};\n"
        : "+f"(d[0]), "+f"(d[1]), "+f"(d[2]), "+f"(d[3])
        : "r"(a0), "r"(a1), "r"(a2), "r"(a3), "r"(b0), "r"(b1));
}

// Scratch for Q, K, V in [B, H, S, Dh] layout
__device__ float g_q[BB * HH * SS * DHD];
__device__ float g_k[BB * HH * SS * DHD];
__device__ float g_v[BB * HH * SS * DHD];

// ---------------------------------------------------------------------------
// QKV projection (unchanged from R2)
// ---------------------------------------------------------------------------
__global__ __launch_bounds__(256) void qkv_kernel(
    const float* __restrict__ X,
    const float* __restrict__ Wq, const float* __restrict__ bq,
    const float* __restrict__ Wk, const float* __restrict__ bk,
    const float* __restrict__ Wv, const float* __restrict__ bv)
{
    const float* W;
    const float* bias;
    float* out;
    if (blockIdx.z == 0)      { W = Wq; bias = bq; out = g_q; }
    else if (blockIdx.z == 1) { W = Wk; bias = bk; out = g_k; }
    else                      { W = Wv; bias = bv; out = g_v; }

    __shared__ __align__(16) float As[8][132];
    __shared__ __align__(16) float Bs[8][132];

    const int tid = threadIdx.x;
    const int m0 = blockIdx.y * 128;
    const int n0 = blockIdx.x * 128;
    const int ld_row = tid >> 1;
    const int ld_k   = (tid & 1) * 4;
    const int ty = tid >> 4, tx = tid & 15;
    const int r0 = ty * 4, c0 = tx * 4;

    ull acc2[8][4];
#pragma unroll
    for (int i = 0; i < 8; i++)
#pragma unroll
        for (int j = 0; j < 4; j++) acc2[i][j] = 0ULL;

    for (int k0 = 0; k0 < DD; k0 += 8) {
        float4 av = *(const float4*)&X[(size_t)(m0 + ld_row) * DD + k0 + ld_k];
        float4 bw = *(const float4*)&W[(size_t)(n0 + ld_row) * DD + k0 + ld_k];
        __syncthreads();
        As[ld_k + 0][ld_row] = av.x; As[ld_k + 1][ld_row] = av.y;
        As[ld_k + 2][ld_row] = av.z; As[ld_k + 3][ld_row] = av.w;
        Bs[ld_k + 0][ld_row] = bw.x; Bs[ld_k + 1][ld_row] = bw.y;
        Bs[ld_k + 2][ld_row] = bw.z; Bs[ld_k + 3][ld_row] = bw.w;
        __syncthreads();

#pragma unroll
        for (int k = 0; k < 8; k++) {
            float a[8];
            *(float4*)&a[0] = *(const float4*)&As[k][r0];
            *(float4*)&a[4] = *(const float4*)&As[k][r0 + 64];
            ull b0 = *(const ull*)&Bs[k][c0];
            ull b1 = *(const ull*)&Bs[k][c0 + 2];
            ull b2 = *(const ull*)&Bs[k][c0 + 64];
            ull b3 = *(const ull*)&Bs[k][c0 + 66];
#pragma unroll
            for (int i = 0; i < 8; i++) {
                ull aa = pk2(a[i], a[i]);
                ffma2(acc2[i][0], aa, b0);
                ffma2(acc2[i][1], aa, b1);
                ffma2(acc2[i][2], aa, b2);
                ffma2(acc2[i][3], aa, b3);
            }
        }
    }

#pragma unroll
    for (int i = 0; i < 8; i++) {
        int row = (i < 4) ? (r0 + i) : (64 + r0 + (i - 4));
        int m = m0 + row;
        int bb = m / SS;
        int s  = m % SS;
        float c[8];
        upk2(c[0], c[1], acc2[i][0]);
        upk2(c[2], c[3], acc2[i][1]);
        upk2(c[4], c[5], acc2[i][2]);
        upk2(c[6], c[7], acc2[i][3]);
#pragma unroll
        for (int j = 0; j < 8; j++) {
            int col = (j < 4) ? (c0 + j) : (64 + c0 + (j - 4));
            int n = n0 + col;
            int h  = n / DHD;
            int dh = n % DHD;
            out[(((size_t)(bb * HH + h)) * SS + s) * DHD + dh] = c[j] + bias[n];
        }
    }
}

// ---------------------------------------------------------------------------
// Flash attention with warp-level mma.sync tf32 (m16n8k8).
// 256 threads / 8 warps, 128 q-rows per CTA, kv tile = 64.
// Warp w owns q-rows [16w, 16w+16). Fragments:
//   A (Q or P): a0=(p, q) a1=(p+8, q) a2=(p, q+4) a3=(p+8, q+4)   p=lane>>2,q=lane&3
//   B (K or V): b0=(k=q, n=p) b1=(k=q+4, n=p)
//   C/D:        c0=(p, 2q) c1=(p, 2q+1) c2=(p+8, 2q) c3=(p+8, 2q+1)
// SMEM pads: Q,K rows 68 floats (frag bank = 4p+q, conflict-free),
//            V rows 72 floats (frag bank = 8q+p, conflict-free).
// Residual/scores accessed directly in fragment layout (32B-sector aligned).
// ---------------------------------------------------------------------------
#define QS_OFF  0
#define KS_OFF  8704            // 128*68
#define VS_OFF  13056           // + 64*68
#define MSK_OFF 17664           // + 64*72
#define SM_FLOATS 17732
#define SM_BYTES (SM_FLOATS * 4)

__global__ __launch_bounds__(256, 2) void attn_mma(
    const float* __restrict__ res,
    const float* __restrict__ mask,
    float* __restrict__ scores_out,
    float* __restrict__ ctx_out)
{
    extern __shared__ float sm[];
    uint32_t* smu = (uint32_t*)sm;

    const int tid = threadIdx.x;
    const int w = tid >> 5, lane = tid & 31;
    const int p = lane >> 2, q = lane & 3;
    const int b = blockIdx.z, h = blockIdx.y;
    const int q0 = blockIdx.x * 128;

    const float* Qg = g_q + (size_t)(b * HH + h) * SS * DHD;
    const float* Kg = g_k + (size_t)(b * HH + h) * SS * DHD;
    const float* Vg = g_v + (size_t)(b * HH + h) * SS * DHD;
    const float* resb  = res        + (size_t)(b * HH + h) * SS * SS;
    float*       soutb = scores_out + (size_t)(b * HH + h) * SS * SS;
    const float* maskb = mask + (size_t)b * SS;

    // Prologue: Q tile [128][64] -> smem (tf32-converted)
#pragma unroll
    for (int g = 0; g < 8; g++) {
        int item = tid + 256 * g;
        int row = item >> 4;
        int c4  = (item & 15) * 4;
        float4 v = *(const float4*)&Qg[(size_t)(q0 + row) * DHD + c4];
        uint4 u;
        u.x = tf32_of(v.x); u.y = tf32_of(v.y);
        u.z = tf32_of(v.z); u.w = tf32_of(v.w);
        *(uint4*)&smu[QS_OFF + row * 68 + c4] = u;
    }

    float o[8][4];
#pragma unroll
    for (int jd = 0; jd < 8; jd++)
#pragma unroll
        for (int i = 0; i < 4; i++) o[jd][i] = 0.f;

    float m0r = -INFINITY, m1r = -INFINITY, l0 = 0.f, l1 = 0.f;
    const int rloc = 16 * w + p;
    const int row0 = q0 + rloc;
    const int row1 = row0 + 8;

    for (int kt = 0; kt < 32; kt++) {
        const int kbase = kt * 64;

        __syncthreads();
        // K tile (tf32) -> pad-68 smem
#pragma unroll
        for (int g = 0; g < 4; g++) {
            int item = tid + 256 * g;
            int row = item >> 4;
            int c4  = (item & 15) * 4;
            float4 v = *(const float4*)&Kg[(size_t)(kbase + row) * DHD + c4];
            uint4 u;
            u.x = tf32_of(v.x); u.y = tf32_of(v.y);
            u.z = tf32_of(v.z); u.w = tf32_of(v.w);
            *(uint4*)&smu[KS_OFF + row * 68 + c4] = u;
        }
        // V tile (tf32) -> pad-72 smem
#pragma unroll
        for (int g = 0; g < 4; g++) {
            int item = tid + 256 * g;
            int row = item >> 4;
            int c4  = (item & 15) * 4;
            float4 v = *(const float4*)&Vg[(size_t)(kbase + row) * DHD + c4];
            uint4 u;
            u.x = tf32_of(v.x); u.y = tf32_of(v.y);
            u.z = tf32_of(v.z); u.w = tf32_of(v.w);
            *(uint4*)&smu[VS_OFF + row * 72 + c4] = u;
        }
        if (tid < 16)
            *(float4*)&sm[MSK_OFF + tid * 4] = *(const float4*)&maskb[kbase + tid * 4];
        __syncthreads();

        // ---- S = Q @ K^T -------------------------------------------------
        float acc[8][4];
#pragma unroll
        for (int j = 0; j < 8; j++)
#pragma unroll
            for (int i = 0; i < 4; i++) acc[j][i] = 0.f;

#pragma unroll
        for (int k = 0; k < 8; k++) {
            uint32_t a0 = smu[QS_OFF + rloc * 68 + 8 * k + q];
            uint32_t a1 = smu[QS_OFF + (rloc + 8) * 68 + 8 * k + q];
            uint32_t a2 = smu[QS_OFF + rloc * 68 + 8 * k + q + 4];
            uint32_t a3 = smu[QS_OFF + (rloc + 8) * 68 + 8 * k + q + 4];
#pragma unroll
            for (int j = 0; j < 8; j++) {
                uint32_t b0 = smu[KS_OFF + (8 * j + p) * 68 + 8 * k + q];
                uint32_t b1 = smu[KS_OFF + (8 * j + p) * 68 + 8 * k + q + 4];
                mma_tf32(acc[j], a0, a1, a2, a3, b0, b1);
            }
        }

        // ---- residual + scores_out + mask + online softmax ---------------
        float rmax0 = -INFINITY, rmax1 = -INFINITY;
#pragma unroll
        for (int j = 0; j < 8; j++) {
            int col = kbase + 8 * j + 2 * q;
            float2 rv0 = *(const float2*)&resb[(size_t)row0 * SS + col];
            float2 rv1 = *(const float2*)&resb[(size_t)row1 * SS + col];
            float s00 = fmaf(acc[j][0], 0.125f, rv0.x);
            float s01 = fmaf(acc[j][1], 0.125f, rv0.y);
            float s10 = fmaf(acc[j][2], 0.125f, rv1.x);
            float s11 = fmaf(acc[j][3], 0.125f, rv1.y);
            *(float2*)&soutb[(size_t)row0 * SS + col] = make_float2(s00, s01);
            *(float2*)&soutb[(size_t)row1 * SS + col] = make_float2(s10, s11);
            float mk0 = sm[MSK_OFF + 8 * j + 2 * q];
            float mk1 = sm[MSK_OFF + 8 * j + 2 * q + 1];
            s00 += mk0; s01 += mk1; s10 += mk0; s11 += mk1;
            acc[j][0] = s00; acc[j][1] = s01; acc[j][2] = s10; acc[j][3] = s11;
            rmax0 = fmaxf(rmax0, fmaxf(s00, s01));
            rmax1 = fmaxf(rmax1, fmaxf(s10, s11));
        }
        rmax0 = fmaxf(rmax0, __shfl_xor_sync(0xffffffffu, rmax0, 1));
        rmax0 = fmaxf(rmax0, __shfl_xor_sync(0xffffffffu, rmax0, 2));
        rmax1 = fmaxf(rmax1, __shfl_xor_sync(0xffffffffu, rmax1, 1));
        rmax1 = fmaxf(rmax1, __shfl_xor_sync(0xffffffffu, rmax1, 2));

        float mn0 = fmaxf(m0r, rmax0);
        float mn1 = fmaxf(m1r, rmax1);
        float al0 = __expf(m0r - mn0);
        float al1 = __expf(m1r - mn1);
        m0r = mn0; m1r = mn1;

        float sum0 = 0.f, sum1 = 0.f;
#pragma unroll
        for (int j = 0; j < 8; j++) {
            float p00 = __expf(acc[j][0] - mn0);
            float p01 = __expf(acc[j][1] - mn0);
            float p10 = __expf(acc[j][2] - mn1);
            float p11 = __expf(acc[j][3] - mn1);
            sum0 += p00 + p01;
            sum1 += p10 + p11;
            acc[j][0] = __uint_as_float(tf32_of(p00));
            acc[j][1] = __uint_as_float(tf32_of(p01));
            acc[j][2] = __uint_as_float(tf32_of(p10));
            acc[j][3] = __uint_as_float(tf32_of(p11));
        }
        sum0 += __shfl_xor_sync(0xffffffffu, sum0, 1);
        sum0 += __shfl_xor_sync(0xffffffffu, sum0, 2);
        sum1 += __shfl_xor_sync(0xffffffffu, sum1, 1);
        sum1 += __shfl_xor_sync(0xffffffffu, sum1, 2);
        l0 = l0 * al0 + sum0;
        l1 = l1 * al1 + sum1;

#pragma unroll
        for (int jd = 0; jd < 8; jd++) {
            o[jd][0] *= al0; o[jd][1] *= al0;
            o[jd][2] *= al1; o[jd][3] *= al1;
        }

        // ---- O += P @ V  (P re-laid C-frag -> A-frag via quad shuffles) ---
#pragma unroll
        for (int jk = 0; jk < 8; jk++) {
            float c0 = acc[jk][0], c1 = acc[jk][1];
            float c2 = acc[jk][2], c3 = acc[jk][3];
            int s1 = q >> 1, s2 = s1 + 2;
            float x00 = __shfl_sync(0xffffffffu, c0, s1, 4);
            float x01 = __shfl_sync(0xffffffffu, c1, s1, 4);
            float x10 = __shfl_sync(0xffffffffu, c2, s1, 4);
            float x11 = __shfl_sync(0xffffffffu, c3, s1, 4);
            float y00 = __shfl_sync(0xffffffffu, c0, s2, 4);
            float y01 = __shfl_sync(0xffffffffu, c1, s2, 4);
            float y10 = __shfl_sync(0xffffffffu, c2, s2, 4);
            float y11 = __shfl_sync(0xffffffffu, c3, s2, 4);
            bool odd = (q & 1);
            uint32_t a0 = __float_as_uint(odd ? x01 : x00);
            uint32_t a1 = __float_as_uint(odd ? x11 : x10);
            uint32_t a2 = __float_as_uint(odd ? y01 : y00);
            uint32_t a3 = __float_as_uint(odd ? y11 : y10);
#pragma unroll
            for (int jd = 0; jd < 8; jd++) {
                uint32_t b0 = smu[VS_OFF + (8 * jk + q) * 72 + 8 * jd + p];
                uint32_t b1 = smu[VS_OFF + (8 * jk + q + 4) * 72 + 8 * jd + p];
                mma_tf32(o[jd], a0, a1, a2, a3, b0, b1);
            }
        }
    }

    // Epilogue: ctx = O / l
    float inv0 = 1.0f / l0;
    float inv1 = 1.0f / l1;
#pragma unroll
    for (int jd = 0; jd < 8; jd++) {
        int col = h * DHD + 8 * jd + 2 * q;
        *(float2*)&ctx_out[(size_t)(b * SS + row0) * DD + col] =
            make_float2(o[jd][0] * inv0, o[jd][1] * inv0);
        *(float2*)&ctx_out[(size_t)(b * SS + row1) * DD + col] =
            make_float2(o[jd][2] * inv1, o[jd][3] * inv1);
    }
}

extern "C" void kernel_launch(void* const* d_in, const int* in_sizes, int n_in,
                              void* d_out, int out_size)
{
    const float* hs   = (const float*)d_in[0];
    const float* mask = (const float*)d_in[1];
    const float* res  = (const float*)d_in[2];
    const float* Wq   = (const float*)d_in[3];
    const float* bq   = (const float*)d_in[4];
    const float* Wk   = (const float*)d_in[5];
    const float* bk   = (const float*)d_in[6];
    const float* Wv   = (const float*)d_in[7];
    const float* bv   = (const float*)d_in[8];

    float* ctx_out    = (float*)d_out;
    float* scores_out = (float*)d_out + (size_t)BB * SS * DD;

    dim3 g1(DD / 128, (BB * SS) / 128, 3);
    qkv_kernel<<<g1, 256>>>(hs, Wq, bq, Wk, bk, Wv, bv);

    cudaFuncSetAttribute(attn_mma, cudaFuncAttributeMaxDynamicSharedMemorySize,
                         SM_BYTES);
    dim3 g2(SS / 128, HH, BB);
    attn_mma<<<g2, 256, SM_BYTES>>>(res, mask, scores_out, ctx_out);
}

// round 7
// speedup vs baseline: 4.2152x; 1.4059x over previous
#include <cuda_runtime.h>
#include <math.h>
#include <cstdint>

#define BB 2
#define SS 2048
#define DD 768
#define HH 12
#define DHD 64

typedef unsigned long long ull;

// ---- tf32 helpers ----------------------------------------------------------
__device__ __forceinline__ uint32_t tf32_of(float f) {
    uint32_t u;
    asm("cvt.rna.tf32.f32 %0, %1;" : "=r"(u) : "f"(f));
    return u;
}
__device__ __forceinline__ void mma_tf32(float* d,
                                         uint32_t a0, uint32_t a1, uint32_t a2, uint32_t a3,
                                         uint32_t b0, uint32_t b1) {
    asm volatile(
        "mma.sync.aligned.m16n8k8.row.col.f32.tf32.tf32.f32 "
        "{%0,%1,%2,%3}, {%4,%5,%6,%7}, {%8,%9}, {%0,%1,%2,%3};\n"
        : "+f"(d[0]), "+f"(d[1]), "+f"(d[2]), "+f"(d[3])
        : "r"(a0), "r"(a1), "r"(a2), "r"(a3), "r"(b0), "r"(b1));
}

// Scratch for Q, K, V in [B, H, S, Dh] layout
__device__ float g_q[BB * HH * SS * DHD];
__device__ float g_k[BB * HH * SS * DHD];
__device__ float g_v[BB * HH * SS * DHD];

// ---------------------------------------------------------------------------
// QKV projection on tensor cores (tf32 mma.sync).
// C[m,n] = sum_k X[m,k] * W[n,k] + bias[n];  M=4096, N=768, K=768.
// CTA tile 128x128, 256 threads / 8 warps: warp (wm = w&3, wn = w>>2)
// owns rows [32*wm, 32*wm+32) (2 m16 tiles) x cols [64*wn, 64*wn+64) (8 n8).
// K-chunks of 32 staged in SMEM (pad 36 -> fragment LDS conflict-free:
// bank = 4p + q). Output scattered into [B,H,S,Dh].
// ---------------------------------------------------------------------------
#define QKV_PAD 36

__global__ __launch_bounds__(256, 2) void qkv_mma(
    const float* __restrict__ X,
    const float* __restrict__ Wq, const float* __restrict__ bq,
    const float* __restrict__ Wk, const float* __restrict__ bk,
    const float* __restrict__ Wv, const float* __restrict__ bv)
{
    const float* W;
    const float* bias;
    float* out;
    if (blockIdx.z == 0)      { W = Wq; bias = bq; out = g_q; }
    else if (blockIdx.z == 1) { W = Wk; bias = bk; out = g_k; }
    else                      { W = Wv; bias = bv; out = g_v; }

    __shared__ __align__(16) uint32_t Xs[128 * QKV_PAD];
    __shared__ __align__(16) uint32_t Ws[128 * QKV_PAD];

    const int tid = threadIdx.x;
    const int w = tid >> 5, lane = tid & 31;
    const int p = lane >> 2, q = lane & 3;
    const int wm = w & 3, wn = w >> 2;
    const int m0 = blockIdx.y * 128;
    const int n0 = blockIdx.x * 128;

    // per-thread staging coords: 4 float4 items each for X and W
    const int ld_row = tid >> 3;          // 0..31 (x4 groups of 32 rows)
    const int ld_c4  = (tid & 7) * 4;     // k-offset within 32-chunk

    float acc[2][8][4];
#pragma unroll
    for (int mt = 0; mt < 2; mt++)
#pragma unroll
        for (int j = 0; j < 8; j++)
#pragma unroll
            for (int i = 0; i < 4; i++) acc[mt][j][i] = 0.f;

    const int arow0 = wm * 32 + p;        // A frag base row (tile mt adds 16)
    const int brow0 = wn * 64 + p;        // B frag base row (tile j adds 8)

    for (int k0 = 0; k0 < DD; k0 += 32) {
        __syncthreads();
#pragma unroll
        for (int g = 0; g < 4; g++) {
            int row = ld_row + 32 * g;
            float4 xv = *(const float4*)&X[(size_t)(m0 + row) * DD + k0 + ld_c4];
            float4 wv = *(const float4*)&W[(size_t)(n0 + row) * DD + k0 + ld_c4];
            uint4 xu, wu;
            xu.x = tf32_of(xv.x); xu.y = tf32_of(xv.y);
            xu.z = tf32_of(xv.z); xu.w = tf32_of(xv.w);
            wu.x = tf32_of(wv.x); wu.y = tf32_of(wv.y);
            wu.z = tf32_of(wv.z); wu.w = tf32_of(wv.w);
            *(uint4*)&Xs[row * QKV_PAD + ld_c4] = xu;
            *(uint4*)&Ws[row * QKV_PAD + ld_c4] = wu;
        }
        __syncthreads();

#pragma unroll
        for (int s = 0; s < 4; s++) {
            uint32_t a[2][4];
#pragma unroll
            for (int mt = 0; mt < 2; mt++) {
                int r = arow0 + 16 * mt;
                a[mt][0] = Xs[r * QKV_PAD + 8 * s + q];
                a[mt][1] = Xs[(r + 8) * QKV_PAD + 8 * s + q];
                a[mt][2] = Xs[r * QKV_PAD + 8 * s + q + 4];
                a[mt][3] = Xs[(r + 8) * QKV_PAD + 8 * s + q + 4];
            }
#pragma unroll
            for (int j = 0; j < 8; j++) {
                int r = brow0 + 8 * j;
                uint32_t b0 = Ws[r * QKV_PAD + 8 * s + q];
                uint32_t b1 = Ws[r * QKV_PAD + 8 * s + q + 4];
#pragma unroll
                for (int mt = 0; mt < 2; mt++)
                    mma_tf32(acc[mt][j], a[mt][0], a[mt][1], a[mt][2], a[mt][3], b0, b1);
            }
        }
    }

    // Epilogue: add bias, scatter rows into [B,H,S,Dh]
#pragma unroll
    for (int mt = 0; mt < 2; mt++) {
        int mA = m0 + wm * 32 + mt * 16 + p;       // rows p and p+8
        int mB = mA + 8;
        int bbA = mA >> 11, sA = mA & 2047;
        int bbB = mB >> 11, sB = mB & 2047;
#pragma unroll
        for (int j = 0; j < 8; j++) {
            int n = n0 + wn * 64 + 8 * j + 2 * q;
            int h = n >> 6, dh = n & 63;
            float2 bv2 = *(const float2*)&bias[n];
            float2 oA = make_float2(acc[mt][j][0] + bv2.x, acc[mt][j][1] + bv2.y);
            float2 oB = make_float2(acc[mt][j][2] + bv2.x, acc[mt][j][3] + bv2.y);
            *(float2*)&out[(((size_t)(bbA * HH + h)) * SS + sA) * DHD + dh] = oA;
            *(float2*)&out[(((size_t)(bbB * HH + h)) * SS + sB) * DHD + dh] = oB;
        }
    }
}

// ---------------------------------------------------------------------------
// Flash attention with warp-level mma.sync tf32 (m16n8k8).  (unchanged, R5)
// ---------------------------------------------------------------------------
#define QS_OFF  0
#define KS_OFF  8704            // 128*68
#define VS_OFF  13056           // + 64*68
#define MSK_OFF 17664           // + 64*72
#define SM_FLOATS 17732
#define SM_BYTES (SM_FLOATS * 4)

__global__ __launch_bounds__(256, 2) void attn_mma(
    const float* __restrict__ res,
    const float* __restrict__ mask,
    float* __restrict__ scores_out,
    float* __restrict__ ctx_out)
{
    extern __shared__ float sm[];
    uint32_t* smu = (uint32_t*)sm;

    const int tid = threadIdx.x;
    const int w = tid >> 5, lane = tid & 31;
    const int p = lane >> 2, q = lane & 3;
    const int b = blockIdx.z, h = blockIdx.y;
    const int q0 = blockIdx.x * 128;

    const float* Qg = g_q + (size_t)(b * HH + h) * SS * DHD;
    const float* Kg = g_k + (size_t)(b * HH + h) * SS * DHD;
    const float* Vg = g_v + (size_t)(b * HH + h) * SS * DHD;
    const float* resb  = res        + (size_t)(b * HH + h) * SS * SS;
    float*       soutb = scores_out + (size_t)(b * HH + h) * SS * SS;
    const float* maskb = mask + (size_t)b * SS;

#pragma unroll
    for (int g = 0; g < 8; g++) {
        int item = tid + 256 * g;
        int row = item >> 4;
        int c4  = (item & 15) * 4;
        float4 v = *(const float4*)&Qg[(size_t)(q0 + row) * DHD + c4];
        uint4 u;
        u.x = tf32_of(v.x); u.y = tf32_of(v.y);
        u.z = tf32_of(v.z); u.w = tf32_of(v.w);
        *(uint4*)&smu[QS_OFF + row * 68 + c4] = u;
    }

    float o[8][4];
#pragma unroll
    for (int jd = 0; jd < 8; jd++)
#pragma unroll
        for (int i = 0; i < 4; i++) o[jd][i] = 0.f;

    float m0r = -INFINITY, m1r = -INFINITY, l0 = 0.f, l1 = 0.f;
    const int rloc = 16 * w + p;
    const int row0 = q0 + rloc;
    const int row1 = row0 + 8;

    for (int kt = 0; kt < 32; kt++) {
        const int kbase = kt * 64;

        __syncthreads();
#pragma unroll
        for (int g = 0; g < 4; g++) {
            int item = tid + 256 * g;
            int row = item >> 4;
            int c4  = (item & 15) * 4;
            float4 v = *(const float4*)&Kg[(size_t)(kbase + row) * DHD + c4];
            uint4 u;
            u.x = tf32_of(v.x); u.y = tf32_of(v.y);
            u.z = tf32_of(v.z); u.w = tf32_of(v.w);
            *(uint4*)&smu[KS_OFF + row * 68 + c4] = u;
        }
#pragma unroll
        for (int g = 0; g < 4; g++) {
            int item = tid + 256 * g;
            int row = item >> 4;
            int c4  = (item & 15) * 4;
            float4 v = *(const float4*)&Vg[(size_t)(kbase + row) * DHD + c4];
            uint4 u;
            u.x = tf32_of(v.x); u.y = tf32_of(v.y);
            u.z = tf32_of(v.z); u.w = tf32_of(v.w);
            *(uint4*)&smu[VS_OFF + row * 72 + c4] = u;
        }
        if (tid < 16)
            *(float4*)&sm[MSK_OFF + tid * 4] = *(const float4*)&maskb[kbase + tid * 4];
        __syncthreads();

        float acc[8][4];
#pragma unroll
        for (int j = 0; j < 8; j++)
#pragma unroll
            for (int i = 0; i < 4; i++) acc[j][i] = 0.f;

#pragma unroll
        for (int k = 0; k < 8; k++) {
            uint32_t a0 = smu[QS_OFF + rloc * 68 + 8 * k + q];
            uint32_t a1 = smu[QS_OFF + (rloc + 8) * 68 + 8 * k + q];
            uint32_t a2 = smu[QS_OFF + rloc * 68 + 8 * k + q + 4];
            uint32_t a3 = smu[QS_OFF + (rloc + 8) * 68 + 8 * k + q + 4];
#pragma unroll
            for (int j = 0; j < 8; j++) {
                uint32_t b0 = smu[KS_OFF + (8 * j + p) * 68 + 8 * k + q];
                uint32_t b1 = smu[KS_OFF + (8 * j + p) * 68 + 8 * k + q + 4];
                mma_tf32(acc[j], a0, a1, a2, a3, b0, b1);
            }
        }

        float rmax0 = -INFINITY, rmax1 = -INFINITY;
#pragma unroll
        for (int j = 0; j < 8; j++) {
            int col = kbase + 8 * j + 2 * q;
            float2 rv0 = *(const float2*)&resb[(size_t)row0 * SS + col];
            float2 rv1 = *(const float2*)&resb[(size_t)row1 * SS + col];
            float s00 = fmaf(acc[j][0], 0.125f, rv0.x);
            float s01 = fmaf(acc[j][1], 0.125f, rv0.y);
            float s10 = fmaf(acc[j][2], 0.125f, rv1.x);
            float s11 = fmaf(acc[j][3], 0.125f, rv1.y);
            *(float2*)&soutb[(size_t)row0 * SS + col] = make_float2(s00, s01);
            *(float2*)&soutb[(size_t)row1 * SS + col] = make_float2(s10, s11);
            float mk0 = sm[MSK_OFF + 8 * j + 2 * q];
            float mk1 = sm[MSK_OFF + 8 * j + 2 * q + 1];
            s00 += mk0; s01 += mk1; s10 += mk0; s11 += mk1;
            acc[j][0] = s00; acc[j][1] = s01; acc[j][2] = s10; acc[j][3] = s11;
            rmax0 = fmaxf(rmax0, fmaxf(s00, s01));
            rmax1 = fmaxf(rmax1, fmaxf(s10, s11));
        }
        rmax0 = fmaxf(rmax0, __shfl_xor_sync(0xffffffffu, rmax0, 1));
        rmax0 = fmaxf(rmax0, __shfl_xor_sync(0xffffffffu, rmax0, 2));
        rmax1 = fmaxf(rmax1, __shfl_xor_sync(0xffffffffu, rmax1, 1));
        rmax1 = fmaxf(rmax1, __shfl_xor_sync(0xffffffffu, rmax1, 2));

        float mn0 = fmaxf(m0r, rmax0);
        float mn1 = fmaxf(m1r, rmax1);
        float al0 = __expf(m0r - mn0);
        float al1 = __expf(m1r - mn1);
        m0r = mn0; m1r = mn1;

        float sum0 = 0.f, sum1 = 0.f;
#pragma unroll
        for (int j = 0; j < 8; j++) {
            float p00 = __expf(acc[j][0] - mn0);
            float p01 = __expf(acc[j][1] - mn0);
            float p10 = __expf(acc[j][2] - mn1);
            float p11 = __expf(acc[j][3] - mn1);
            sum0 += p00 + p01;
            sum1 += p10 + p11;
            acc[j][0] = __uint_as_float(tf32_of(p00));
            acc[j][1] = __uint_as_float(tf32_of(p01));
            acc[j][2] = __uint_as_float(tf32_of(p10));
            acc[j][3] = __uint_as_float(tf32_of(p11));
        }
        sum0 += __shfl_xor_sync(0xffffffffu, sum0, 1);
        sum0 += __shfl_xor_sync(0xffffffffu, sum0, 2);
        sum1 += __shfl_xor_sync(0xffffffffu, sum1, 1);
        sum1 += __shfl_xor_sync(0xffffffffu, sum1, 2);
        l0 = l0 * al0 + sum0;
        l1 = l1 * al1 + sum1;

#pragma unroll
        for (int jd = 0; jd < 8; jd++) {
            o[jd][0] *= al0; o[jd][1] *= al0;
            o[jd][2] *= al1; o[jd][3] *= al1;
        }

#pragma unroll
        for (int jk = 0; jk < 8; jk++) {
            float c0 = acc[jk][0], c1 = acc[jk][1];
            float c2 = acc[jk][2], c3 = acc[jk][3];
            int s1 = q >> 1, s2 = s1 + 2;
            float x00 = __shfl_sync(0xffffffffu, c0, s1, 4);
            float x01 = __shfl_sync(0xffffffffu, c1, s1, 4);
            float x10 = __shfl_sync(0xffffffffu, c2, s1, 4);
            float x11 = __shfl_sync(0xffffffffu, c3, s1, 4);
            float y00 = __shfl_sync(0xffffffffu, c0, s2, 4);
            float y01 = __shfl_sync(0xffffffffu, c1, s2, 4);
            float y10 = __shfl_sync(0xffffffffu, c2, s2, 4);
            float y11 = __shfl_sync(0xffffffffu, c3, s2, 4);
            bool odd = (q & 1);
            uint32_t a0 = __float_as_uint(odd ? x01 : x00);
            uint32_t a1 = __float_as_uint(odd ? x11 : x10);
            uint32_t a2 = __float_as_uint(odd ? y01 : y00);
            uint32_t a3 = __float_as_uint(odd ? y11 : y10);
#pragma unroll
            for (int jd = 0; jd < 8; jd++) {
                uint32_t b0 = smu[VS_OFF + (8 * jk + q) * 72 + 8 * jd + p];
                uint32_t b1 = smu[VS_OFF + (8 * jk + q + 4) * 72 + 8 * jd + p];
                mma_tf32(o[jd], a0, a1, a2, a3, b0, b1);
            }
        }
    }

    float inv0 = 1.0f / l0;
    float inv1 = 1.0f / l1;
#pragma unroll
    for (int jd = 0; jd < 8; jd++) {
        int col = h * DHD + 8 * jd + 2 * q;
        *(float2*)&ctx_out[(size_t)(b * SS + row0) * DD + col] =
            make_float2(o[jd][0] * inv0, o[jd][1] * inv0);
        *(float2*)&ctx_out[(size_t)(b * SS + row1) * DD + col] =
            make_float2(o[jd][2] * inv1, o[jd][3] * inv1);
    }
}

extern "C" void kernel_launch(void* const* d_in, const int* in_sizes, int n_in,
                              void* d_out, int out_size)
{
    const float* hs   = (const float*)d_in[0];
    const float* mask = (const float*)d_in[1];
    const float* res  = (const float*)d_in[2];
    const float* Wq   = (const float*)d_in[3];
    const float* bq   = (const float*)d_in[4];
    const float* Wk   = (const float*)d_in[5];
    const float* bk   = (const float*)d_in[6];
    const float* Wv   = (const float*)d_in[7];
    const float* bv   = (const float*)d_in[8];

    float* ctx_out    = (float*)d_out;
    float* scores_out = (float*)d_out + (size_t)BB * SS * DD;

    dim3 g1(DD / 128, (BB * SS) / 128, 3);
    qkv_mma<<<g1, 256>>>(hs, Wq, bq, Wk, bk, Wv, bv);

    cudaFuncSetAttribute(attn_mma, cudaFuncAttributeMaxDynamicSharedMemorySize,
                         SM_BYTES);
    dim3 g2(SS / 128, HH, BB);
    attn_mma<<<g2, 256, SM_BYTES>>>(res, mask, scores_out, ctx_out);
}

// round 8
// speedup vs baseline: 4.6898x; 1.1126x over previous
#include <cuda_runtime.h>
#include <math.h>
#include <cstdint>

#define BB 2
#define SS 2048
#define DD 768
#define HH 12
#define DHD 64

// ---- tf32 helpers ----------------------------------------------------------
__device__ __forceinline__ uint32_t tf32_of(float f) {
    uint32_t u;
    asm("cvt.rna.tf32.f32 %0, %1;" : "=r"(u) : "f"(f));
    return u;
}
__device__ __forceinline__ void mma_tf32(float* d,
                                         uint32_t a0, uint32_t a1, uint32_t a2, uint32_t a3,
                                         uint32_t b0, uint32_t b1) {
    asm volatile(
        "mma.sync.aligned.m16n8k8.row.col.f32.tf32.tf32.f32 "
        "{%0,%1,%2,%3}, {%4,%5,%6,%7}, {%8,%9}, {%0,%1,%2,%3};\n"
        : "+f"(d[0]), "+f"(d[1]), "+f"(d[2]), "+f"(d[3])
        : "r"(a0), "r"(a1), "r"(a2), "r"(a3), "r"(b0), "r"(b1));
}

// Scratch for Q, K, V in [B, H, S, Dh] layout
__device__ float g_q[BB * HH * SS * DHD];
__device__ float g_k[BB * HH * SS * DHD];
__device__ float g_v[BB * HH * SS * DHD];

// ---------------------------------------------------------------------------
// QKV projection on tensor cores (tf32 mma.sync).  (unchanged from R6)
// ---------------------------------------------------------------------------
#define QKV_PAD 36

__global__ __launch_bounds__(256, 2) void qkv_mma(
    const float* __restrict__ X,
    const float* __restrict__ Wq, const float* __restrict__ bq,
    const float* __restrict__ Wk, const float* __restrict__ bk,
    const float* __restrict__ Wv, const float* __restrict__ bv)
{
    const float* W;
    const float* bias;
    float* out;
    if (blockIdx.z == 0)      { W = Wq; bias = bq; out = g_q; }
    else if (blockIdx.z == 1) { W = Wk; bias = bk; out = g_k; }
    else                      { W = Wv; bias = bv; out = g_v; }

    __shared__ __align__(16) uint32_t Xs[128 * QKV_PAD];
    __shared__ __align__(16) uint32_t Ws[128 * QKV_PAD];

    const int tid = threadIdx.x;
    const int w = tid >> 5, lane = tid & 31;
    const int p = lane >> 2, q = lane & 3;
    const int wm = w & 3, wn = w >> 2;
    const int m0 = blockIdx.y * 128;
    const int n0 = blockIdx.x * 128;

    const int ld_row = tid >> 3;
    const int ld_c4  = (tid & 7) * 4;

    float acc[2][8][4];
#pragma unroll
    for (int mt = 0; mt < 2; mt++)
#pragma unroll
        for (int j = 0; j < 8; j++)
#pragma unroll
            for (int i = 0; i < 4; i++) acc[mt][j][i] = 0.f;

    const int arow0 = wm * 32 + p;
    const int brow0 = wn * 64 + p;

    for (int k0 = 0; k0 < DD; k0 += 32) {
        __syncthreads();
#pragma unroll
        for (int g = 0; g < 4; g++) {
            int row = ld_row + 32 * g;
            float4 xv = *(const float4*)&X[(size_t)(m0 + row) * DD + k0 + ld_c4];
            float4 wv = *(const float4*)&W[(size_t)(n0 + row) * DD + k0 + ld_c4];
            uint4 xu, wu;
            xu.x = tf32_of(xv.x); xu.y = tf32_of(xv.y);
            xu.z = tf32_of(xv.z); xu.w = tf32_of(xv.w);
            wu.x = tf32_of(wv.x); wu.y = tf32_of(wv.y);
            wu.z = tf32_of(wv.z); wu.w = tf32_of(wv.w);
            *(uint4*)&Xs[row * QKV_PAD + ld_c4] = xu;
            *(uint4*)&Ws[row * QKV_PAD + ld_c4] = wu;
        }
        __syncthreads();

#pragma unroll
        for (int s = 0; s < 4; s++) {
            uint32_t a[2][4];
#pragma unroll
            for (int mt = 0; mt < 2; mt++) {
                int r = arow0 + 16 * mt;
                a[mt][0] = Xs[r * QKV_PAD + 8 * s + q];
                a[mt][1] = Xs[(r + 8) * QKV_PAD + 8 * s + q];
                a[mt][2] = Xs[r * QKV_PAD + 8 * s + q + 4];
                a[mt][3] = Xs[(r + 8) * QKV_PAD + 8 * s + q + 4];
            }
#pragma unroll
            for (int j = 0; j < 8; j++) {
                int r = brow0 + 8 * j;
                uint32_t b0 = Ws[r * QKV_PAD + 8 * s + q];
                uint32_t b1 = Ws[r * QKV_PAD + 8 * s + q + 4];
#pragma unroll
                for (int mt = 0; mt < 2; mt++)
                    mma_tf32(acc[mt][j], a[mt][0], a[mt][1], a[mt][2], a[mt][3], b0, b1);
            }
        }
    }

#pragma unroll
    for (int mt = 0; mt < 2; mt++) {
        int mA = m0 + wm * 32 + mt * 16 + p;
        int mB = mA + 8;
        int bbA = mA >> 11, sA = mA & 2047;
        int bbB = mB >> 11, sB = mB & 2047;
#pragma unroll
        for (int j = 0; j < 8; j++) {
            int n = n0 + wn * 64 + 8 * j + 2 * q;
            int h = n >> 6, dh = n & 63;
            float2 bv2 = *(const float2*)&bias[n];
            float2 oA = make_float2(acc[mt][j][0] + bv2.x, acc[mt][j][1] + bv2.y);
            float2 oB = make_float2(acc[mt][j][2] + bv2.x, acc[mt][j][3] + bv2.y);
            *(float2*)&out[(((size_t)(bbA * HH + h)) * SS + sA) * DHD + dh] = oA;
            *(float2*)&out[(((size_t)(bbB * HH + h)) * SS + sB) * DHD + dh] = oB;
        }
    }
}

// ---------------------------------------------------------------------------
// Flash attention, mma.sync tf32. 128 threads / 4 warps, warp owns 32 q-rows
// (two m16 tiles) -> K/V B-fragments reused x2, LDS/MMA drops 40%.
// 3 CTAs/SM (smem 70.9KB, regs <= 170).
// ---------------------------------------------------------------------------
#define QS_OFF  0
#define KS_OFF  8704            // 128*68
#define VS_OFF  13056           // + 64*68
#define MSK_OFF 17664           // + 64*72
#define SM_FLOATS 17732
#define SM_BYTES (SM_FLOATS * 4)

__global__ __launch_bounds__(128, 3) void attn_mma(
    const float* __restrict__ res,
    const float* __restrict__ mask,
    float* __restrict__ scores_out,
    float* __restrict__ ctx_out)
{
    extern __shared__ float sm[];
    uint32_t* smu = (uint32_t*)sm;

    const int tid = threadIdx.x;
    const int w = tid >> 5, lane = tid & 31;
    const int p = lane >> 2, q = lane & 3;
    const int b = blockIdx.z, h = blockIdx.y;
    const int q0 = blockIdx.x * 128;

    const float* Qg = g_q + (size_t)(b * HH + h) * SS * DHD;
    const float* Kg = g_k + (size_t)(b * HH + h) * SS * DHD;
    const float* Vg = g_v + (size_t)(b * HH + h) * SS * DHD;
    const float* resb  = res        + (size_t)(b * HH + h) * SS * SS;
    float*       soutb = scores_out + (size_t)(b * HH + h) * SS * SS;
    const float* maskb = mask + (size_t)b * SS;

    // Q tile [128][64] -> smem (tf32)
#pragma unroll
    for (int g = 0; g < 16; g++) {
        int item = tid + 128 * g;
        int row = item >> 4;
        int c4  = (item & 15) * 4;
        float4 v = *(const float4*)&Qg[(size_t)(q0 + row) * DHD + c4];
        uint4 u;
        u.x = tf32_of(v.x); u.y = tf32_of(v.y);
        u.z = tf32_of(v.z); u.w = tf32_of(v.w);
        *(uint4*)&smu[QS_OFF + row * 68 + c4] = u;
    }

    float o[2][8][4];
#pragma unroll
    for (int mt = 0; mt < 2; mt++)
#pragma unroll
        for (int jd = 0; jd < 8; jd++)
#pragma unroll
            for (int i = 0; i < 4; i++) o[mt][jd][i] = 0.f;

    float mr[2][2], lr[2][2];
#pragma unroll
    for (int mt = 0; mt < 2; mt++) {
        mr[mt][0] = -INFINITY; mr[mt][1] = -INFINITY;
        lr[mt][0] = 0.f;       lr[mt][1] = 0.f;
    }

    const int rb = 32 * w;                 // warp's row base (local)

    for (int kt = 0; kt < 32; kt++) {
        const int kbase = kt * 64;

        __syncthreads();
#pragma unroll
        for (int g = 0; g < 8; g++) {
            int item = tid + 128 * g;
            int row = item >> 4;
            int c4  = (item & 15) * 4;
            float4 v = *(const float4*)&Kg[(size_t)(kbase + row) * DHD + c4];
            uint4 u;
            u.x = tf32_of(v.x); u.y = tf32_of(v.y);
            u.z = tf32_of(v.z); u.w = tf32_of(v.w);
            *(uint4*)&smu[KS_OFF + row * 68 + c4] = u;
        }
#pragma unroll
        for (int g = 0; g < 8; g++) {
            int item = tid + 128 * g;
            int row = item >> 4;
            int c4  = (item & 15) * 4;
            float4 v = *(const float4*)&Vg[(size_t)(kbase + row) * DHD + c4];
            uint4 u;
            u.x = tf32_of(v.x); u.y = tf32_of(v.y);
            u.z = tf32_of(v.z); u.w = tf32_of(v.w);
            *(uint4*)&smu[VS_OFF + row * 72 + c4] = u;
        }
        if (tid < 16)
            *(float4*)&sm[MSK_OFF + tid * 4] = *(const float4*)&maskb[kbase + tid * 4];
        __syncthreads();

        // ---- S = Q @ K^T (two m16 tiles share B fragments) ----------------
        float acc[2][8][4];
#pragma unroll
        for (int mt = 0; mt < 2; mt++)
#pragma unroll
            for (int j = 0; j < 8; j++)
#pragma unroll
                for (int i = 0; i < 4; i++) acc[mt][j][i] = 0.f;

#pragma unroll
        for (int k = 0; k < 8; k++) {
            uint32_t a[2][4];
#pragma unroll
            for (int mt = 0; mt < 2; mt++) {
                int r = rb + 16 * mt + p;
                a[mt][0] = smu[QS_OFF + r * 68 + 8 * k + q];
                a[mt][1] = smu[QS_OFF + (r + 8) * 68 + 8 * k + q];
                a[mt][2] = smu[QS_OFF + r * 68 + 8 * k + q + 4];
                a[mt][3] = smu[QS_OFF + (r + 8) * 68 + 8 * k + q + 4];
            }
#pragma unroll
            for (int j = 0; j < 8; j++) {
                uint32_t b0 = smu[KS_OFF + (8 * j + p) * 68 + 8 * k + q];
                uint32_t b1 = smu[KS_OFF + (8 * j + p) * 68 + 8 * k + q + 4];
                mma_tf32(acc[0][j], a[0][0], a[0][1], a[0][2], a[0][3], b0, b1);
                mma_tf32(acc[1][j], a[1][0], a[1][1], a[1][2], a[1][3], b0, b1);
            }
        }

        // ---- residual + scores_out + mask + online softmax (per tile) -----
        float alpha[2][2];
#pragma unroll
        for (int mt = 0; mt < 2; mt++) {
            const int row0 = q0 + rb + 16 * mt + p;
            const int row1 = row0 + 8;
            float rmax0 = -INFINITY, rmax1 = -INFINITY;
#pragma unroll
            for (int j = 0; j < 8; j++) {
                int col = kbase + 8 * j + 2 * q;
                float2 rv0 = *(const float2*)&resb[(size_t)row0 * SS + col];
                float2 rv1 = *(const float2*)&resb[(size_t)row1 * SS + col];
                float s00 = fmaf(acc[mt][j][0], 0.125f, rv0.x);
                float s01 = fmaf(acc[mt][j][1], 0.125f, rv0.y);
                float s10 = fmaf(acc[mt][j][2], 0.125f, rv1.x);
                float s11 = fmaf(acc[mt][j][3], 0.125f, rv1.y);
                *(float2*)&soutb[(size_t)row0 * SS + col] = make_float2(s00, s01);
                *(float2*)&soutb[(size_t)row1 * SS + col] = make_float2(s10, s11);
                float mk0 = sm[MSK_OFF + 8 * j + 2 * q];
                float mk1 = sm[MSK_OFF + 8 * j + 2 * q + 1];
                s00 += mk0; s01 += mk1; s10 += mk0; s11 += mk1;
                acc[mt][j][0] = s00; acc[mt][j][1] = s01;
                acc[mt][j][2] = s10; acc[mt][j][3] = s11;
                rmax0 = fmaxf(rmax0, fmaxf(s00, s01));
                rmax1 = fmaxf(rmax1, fmaxf(s10, s11));
            }
            rmax0 = fmaxf(rmax0, __shfl_xor_sync(0xffffffffu, rmax0, 1));
            rmax0 = fmaxf(rmax0, __shfl_xor_sync(0xffffffffu, rmax0, 2));
            rmax1 = fmaxf(rmax1, __shfl_xor_sync(0xffffffffu, rmax1, 1));
            rmax1 = fmaxf(rmax1, __shfl_xor_sync(0xffffffffu, rmax1, 2));

            float mn0 = fmaxf(mr[mt][0], rmax0);
            float mn1 = fmaxf(mr[mt][1], rmax1);
            float al0 = __expf(mr[mt][0] - mn0);
            float al1 = __expf(mr[mt][1] - mn1);
            mr[mt][0] = mn0; mr[mt][1] = mn1;

            float sum0 = 0.f, sum1 = 0.f;
#pragma unroll
            for (int j = 0; j < 8; j++) {
                float p00 = __expf(acc[mt][j][0] - mn0);
                float p01 = __expf(acc[mt][j][1] - mn0);
                float p10 = __expf(acc[mt][j][2] - mn1);
                float p11 = __expf(acc[mt][j][3] - mn1);
                sum0 += p00 + p01;
                sum1 += p10 + p11;
                acc[mt][j][0] = __uint_as_float(tf32_of(p00));
                acc[mt][j][1] = __uint_as_float(tf32_of(p01));
                acc[mt][j][2] = __uint_as_float(tf32_of(p10));
                acc[mt][j][3] = __uint_as_float(tf32_of(p11));
            }
            sum0 += __shfl_xor_sync(0xffffffffu, sum0, 1);
            sum0 += __shfl_xor_sync(0xffffffffu, sum0, 2);
            sum1 += __shfl_xor_sync(0xffffffffu, sum1, 1);
            sum1 += __shfl_xor_sync(0xffffffffu, sum1, 2);
            lr[mt][0] = lr[mt][0] * al0 + sum0;
            lr[mt][1] = lr[mt][1] * al1 + sum1;
            alpha[mt][0] = al0; alpha[mt][1] = al1;

#pragma unroll
            for (int jd = 0; jd < 8; jd++) {
                o[mt][jd][0] *= al0; o[mt][jd][1] *= al0;
                o[mt][jd][2] *= al1; o[mt][jd][3] *= al1;
            }
        }

        // ---- O += P @ V (B fragments shared across tiles) -----------------
#pragma unroll
        for (int jk = 0; jk < 8; jk++) {
            uint32_t aA[2][4];
#pragma unroll
            for (int mt = 0; mt < 2; mt++) {
                float c0 = acc[mt][jk][0], c1 = acc[mt][jk][1];
                float c2 = acc[mt][jk][2], c3 = acc[mt][jk][3];
                int s1 = q >> 1, s2 = s1 + 2;
                float x00 = __shfl_sync(0xffffffffu, c0, s1, 4);
                float x01 = __shfl_sync(0xffffffffu, c1, s1, 4);
                float x10 = __shfl_sync(0xffffffffu, c2, s1, 4);
                float x11 = __shfl_sync(0xffffffffu, c3, s1, 4);
                float y00 = __shfl_sync(0xffffffffu, c0, s2, 4);
                float y01 = __shfl_sync(0xffffffffu, c1, s2, 4);
                float y10 = __shfl_sync(0xffffffffu, c2, s2, 4);
                float y11 = __shfl_sync(0xffffffffu, c3, s2, 4);
                bool odd = (q & 1);
                aA[mt][0] = __float_as_uint(odd ? x01 : x00);
                aA[mt][1] = __float_as_uint(odd ? x11 : x10);
                aA[mt][2] = __float_as_uint(odd ? y01 : y00);
                aA[mt][3] = __float_as_uint(odd ? y11 : y10);
            }
#pragma unroll
            for (int jd = 0; jd < 8; jd++) {
                uint32_t b0 = smu[VS_OFF + (8 * jk + q) * 72 + 8 * jd + p];
                uint32_t b1 = smu[VS_OFF + (8 * jk + q + 4) * 72 + 8 * jd + p];
                mma_tf32(o[0][jd], aA[0][0], aA[0][1], aA[0][2], aA[0][3], b0, b1);
                mma_tf32(o[1][jd], aA[1][0], aA[1][1], aA[1][2], aA[1][3], b0, b1);
            }
        }
    }

    // Epilogue
#pragma unroll
    for (int mt = 0; mt < 2; mt++) {
        const int row0 = q0 + rb + 16 * mt + p;
        const int row1 = row0 + 8;
        float inv0 = 1.0f / lr[mt][0];
        float inv1 = 1.0f / lr[mt][1];
#pragma unroll
        for (int jd = 0; jd < 8; jd++) {
            int col = h * DHD + 8 * jd + 2 * q;
            *(float2*)&ctx_out[(size_t)(b * SS + row0) * DD + col] =
                make_float2(o[mt][jd][0] * inv0, o[mt][jd][1] * inv0);
            *(float2*)&ctx_out[(size_t)(b * SS + row1) * DD + col] =
                make_float2(o[mt][jd][2] * inv1, o[mt][jd][3] * inv1);
        }
    }
}

extern "C" void kernel_launch(void* const* d_in, const int* in_sizes, int n_in,
                              void* d_out, int out_size)
{
    const float* hs   = (const float*)d_in[0];
    const float* mask = (const float*)d_in[1];
    const float* res  = (const float*)d_in[2];
    const float* Wq   = (const float*)d_in[3];
    const float* bq   = (const float*)d_in[4];
    const float* Wk   = (const float*)d_in[5];
    const float* bk   = (const float*)d_in[6];
    const float* Wv   = (const float*)d_in[7];
    const float* bv   = (const float*)d_in[8];

    float* ctx_out    = (float*)d_out;
    float* scores_out = (float*)d_out + (size_t)BB * SS * DD;

    dim3 g1(DD / 128, (BB * SS) / 128, 3);
    qkv_mma<<<g1, 256>>>(hs, Wq, bq, Wk, bk, Wv, bv);

    cudaFuncSetAttribute(attn_mma, cudaFuncAttributeMaxDynamicSharedMemorySize,
                         SM_BYTES);
    dim3 g2(SS / 128, HH, BB);
    attn_mma<<<g2, 128, SM_BYTES>>>(res, mask, scores_out, ctx_out);
}